// round 6
// baseline (speedup 1.0000x reference)
#include <cuda_runtime.h>
#include <cuda_bf16.h>

// Problem constants (from reference setup_inputs)
#define BH   16      // b*h = 2*8
#define LSEQ 4096
#define DH   128     // dk = dv
#define CC   32      // chunk size
#define NCH  128     // LSEQ / CC
#define SP   132     // padded shared row stride (floats)
#define NSLICE 8
#define DVS  16      // dv per scan CTA
#define O_ELEMS (BH * LSEQ * DH)   // 8388608
#define S_ELEMS (BH * DH * DH)     // 262144

// ---------------- device scratch (no allocations allowed) ----------------
__device__ float g_qn[BH * LSEQ * DH];
__device__ float g_kn[BH * LSEQ * DH];
__device__ float g_w [BH * LSEQ * DH];
__device__ float g_u [BH * LSEQ * DH];
__device__ float g_attl[BH * NCH * CC * CC];

// ===========================================================================
// Phase 1: per-(head,chunk) local work. Grid = 2048, 128 threads.
//   - l2norm q,k ; v*=beta ; kb = k*beta
//   - A = -(kb @ k^T) strictly-lower ; forward substitution ; +I ; bf16 round
//   - u = T @ v ; w = T @ kb ; att_local = tril(q @ k^T)  (incl. diagonal)
// ===========================================================================
extern "C" __global__ void __launch_bounds__(128)
deltanet_prep(const float* __restrict__ q, const float* __restrict__ k,
              const float* __restrict__ v, const float* __restrict__ beta)
{
    extern __shared__ float sm[];
    float* sq   = sm;                 // 32*132
    float* sk   = sq  + CC * SP;      // 32*132
    float* skb  = sk  + CC * SP;      // 32*132
    float* sv   = skb + CC * SP;      // 32*132
    float* sT   = sv  + CC * SP;      // 32*33
    float* sbet = sT  + CC * 33;      // 32
    float* sps  = sbet + CC;          // 32*8 partials (q:0..3, k:4..7)

    const int tid   = threadIdx.x;
    const int head  = blockIdx.x >> 7;        // / NCH
    const int chunk = blockIdx.x & (NCH - 1);
    const size_t gbase = ((size_t)head * LSEQ + (size_t)chunk * CC) * DH;

    // ---- load q,k,v tile (float4) into padded shared ----
    for (int i = tid; i < CC * DH / 4; i += 128) {
        int r = i >> 5, d4 = (i & 31) << 2;
        *(float4*)(sq + r * SP + d4) = *(const float4*)(q + gbase + r * DH + d4);
        *(float4*)(sk + r * SP + d4) = *(const float4*)(k + gbase + r * DH + d4);
        *(float4*)(sv + r * SP + d4) = *(const float4*)(v + gbase + r * DH + d4);
    }
    if (tid < CC) sbet[tid] = beta[(size_t)head * LSEQ + (size_t)chunk * CC + tid];
    __syncthreads();

    // ---- row sum-of-squares (4 partials per row) ----
    {
        int r = tid >> 2, p = tid & 3;
        float aq = 0.f, ak = 0.f;
        int d0 = p * 32;
        #pragma unroll 8
        for (int d = d0; d < d0 + 32; d++) {
            float xv = sq[r * SP + d]; aq += xv * xv;
            float yv = sk[r * SP + d]; ak += yv * yv;
        }
        sps[r * 8 + p]     = aq;
        sps[r * 8 + 4 + p] = ak;
    }
    __syncthreads();
    if (tid < CC) {
        float aq = sps[tid*8+0] + sps[tid*8+1] + sps[tid*8+2] + sps[tid*8+3];
        float ak = sps[tid*8+4] + sps[tid*8+5] + sps[tid*8+6] + sps[tid*8+7];
        sps[tid * 8]     = rsqrtf(aq + 1e-6f);
        sps[tid * 8 + 4] = rsqrtf(ak + 1e-6f);
    }
    __syncthreads();
    // ---- normalize + beta-scale ----
    for (int i = tid; i < CC * DH; i += 128) {
        int r = i >> 7, d = i & 127;
        int idx = r * SP + d;
        float qv = sq[idx] * sps[r * 8];
        float kv = sk[idx] * sps[r * 8 + 4];
        sq[idx]  = qv;
        sk[idx]  = kv;
        skb[idx] = kv * sbet[r];
        sv[idx] *= sbet[r];
    }
    __syncthreads();

    // ---- A[i][j] = -(kb[i] . k[j]) for j<i, else 0 ----
    {
        int i = tid >> 2, jq = tid & 3;
        float acc[8];
        #pragma unroll
        for (int jj = 0; jj < 8; jj++) acc[jj] = 0.f;
        for (int d = 0; d < DH; d++) {
            float kbv = skb[i * SP + d];
            #pragma unroll
            for (int jj = 0; jj < 8; jj++)
                acc[jj] += kbv * sk[(jq + 4 * jj) * SP + d];
        }
        #pragma unroll
        for (int jj = 0; jj < 8; jj++) {
            int j = jq + 4 * jj;
            sT[i * 33 + j] = (j < i) ? -acc[jj] : 0.f;
        }
    }
    __syncthreads();

    // ---- forward substitution on warp 0 (sequential over rows) ----
    if (tid < 32) {
        int m = tid;
        for (int i = 1; i < CC; i++) {
            float upd = 0.f;
            if (m < i) {
                for (int j = 0; j < i; j++)
                    upd += sT[i * 33 + j] * sT[j * 33 + m];
            }
            __syncwarp();
            if (m < i) sT[i * 33 + m] += upd;
            __syncwarp();
        }
    }
    __syncthreads();
    // ---- add I, then replicate reference bf16 round-trip ----
    for (int idx = tid; idx < CC * CC; idx += 128) {
        int i = idx >> 5, j = idx & 31;
        float tv = sT[i * 33 + j] + (i == j ? 1.f : 0.f);
        sT[i * 33 + j] = __bfloat162float(__float2bfloat16(tv));
    }
    __syncthreads();

    // ---- u = T @ (v*beta), w = T @ kb : thread = (row, 8 strided float4 cols) ----
    {
        int r = tid >> 2;
        int cb = (tid & 3) << 2;     // base col of float4; chunks at cb + 16*kk
        float4 au[8], aw[8];
        #pragma unroll
        for (int kk = 0; kk < 8; kk++) {
            au[kk] = make_float4(0.f, 0.f, 0.f, 0.f);
            aw[kk] = make_float4(0.f, 0.f, 0.f, 0.f);
        }
        for (int j = 0; j < CC; j++) {
            float t = sT[r * 33 + j];
            #pragma unroll
            for (int kk = 0; kk < 8; kk++) {
                float4 vv = *(float4*)(sv  + j * SP + cb + 16 * kk);
                float4 kb = *(float4*)(skb + j * SP + cb + 16 * kk);
                au[kk].x += t * vv.x; au[kk].y += t * vv.y;
                au[kk].z += t * vv.z; au[kk].w += t * vv.w;
                aw[kk].x += t * kb.x; aw[kk].y += t * kb.y;
                aw[kk].z += t * kb.z; aw[kk].w += t * kb.w;
            }
        }
        #pragma unroll
        for (int kk = 0; kk < 8; kk++) {
            *(float4*)(g_u + gbase + r * DH + cb + 16 * kk) = au[kk];
            *(float4*)(g_w + gbase + r * DH + cb + 16 * kk) = aw[kk];
        }
    }

    // ---- att_local = tril(q @ k^T) including diagonal ----
    {
        int i = tid >> 2, jq = tid & 3;
        float acc[8];
        #pragma unroll
        for (int jj = 0; jj < 8; jj++) acc[jj] = 0.f;
        for (int d = 0; d < DH; d++) {
            float qv = sq[i * SP + d];
            #pragma unroll
            for (int jj = 0; jj < 8; jj++)
                acc[jj] += qv * sk[(jq + 4 * jj) * SP + d];
        }
        size_t ab = ((size_t)(head * NCH + chunk)) * CC * CC;
        #pragma unroll
        for (int jj = 0; jj < 8; jj++) {
            int j = jq + 4 * jj;
            g_attl[ab + i * CC + j] = (j <= i) ? acc[jj] : 0.f;
        }
    }

    // ---- persist normalized q,k ----
    for (int i = tid; i < CC * DH / 4; i += 128) {
        int r = i >> 5, d4 = (i & 31) << 2;
        *(float4*)(g_qn + gbase + r * DH + d4) = *(float4*)(sq + r * SP + d4);
        *(float4*)(g_kn + gbase + r * DH + d4) = *(float4*)(sk + r * SP + d4);
    }
}

// ===========================================================================
// Phase 2: sequential scan over chunks, per (head, dv-slice).
// Grid = 16*8 = 128 CTAs, 256 threads. S[128 x 16] lives in shared (fp32).
// ===========================================================================
extern "C" __global__ void __launch_bounds__(256)
deltanet_scan(float* __restrict__ out, long long out_size)
{
    extern __shared__ float sm2[];
    float* s_w    = sm2;                 // 32*132
    float* s_q    = s_w    + CC * SP;    // 32*132
    float* s_k    = s_q    + CC * SP;    // 32*132
    float* s_attl = s_k    + CC * SP;    // 1024
    float* s_u    = s_attl + CC * CC;    // 512
    float* s_un   = s_u    + CC * DVS;   // 512
    float* s_S    = s_un   + CC * DVS;   // 128*17

    const int tid  = threadIdx.x;
    const int head = blockIdx.x >> 3;
    const int sl   = blockIdx.x & 7;
    const int coff = sl * DVS;

    for (int i = tid; i < DH * 17; i += 256) s_S[i] = 0.f;
    __syncthreads();

    const int c  = tid & 15;
    const int rr = tid >> 4;     // 0..15
    const int r0 = rr, r1 = rr + 16;
    const int db = rr * 8;       // S-update d base (reuse rr as d-group)

    for (int t = 0; t < NCH; t++) {
        const size_t gb = ((size_t)head * LSEQ + (size_t)t * CC) * DH;

        // ---- stage w, q, k, u-slice, att_local ----
        for (int i = tid; i < CC * DH / 4; i += 256) {
            int r = i >> 5, d4 = (i & 31) << 2;
            *(float4*)(s_w + r * SP + d4) = *(const float4*)(g_w  + gb + r * DH + d4);
            *(float4*)(s_q + r * SP + d4) = *(const float4*)(g_qn + gb + r * DH + d4);
            *(float4*)(s_k + r * SP + d4) = *(const float4*)(g_kn + gb + r * DH + d4);
        }
        for (int i = tid; i < CC * DVS; i += 256) {
            int r = i >> 4, cc2 = i & 15;
            s_u[i] = g_u[gb + r * DH + coff + cc2];
        }
        {
            size_t ab = ((size_t)(head * NCH + t)) * CC * CC;
            for (int i = tid; i < CC * CC; i += 256) s_attl[i] = g_attl[ab + i];
        }
        __syncthreads();

        // ---- u_new = u - w @ S ----
        float a0 = 0.f, a1 = 0.f;
        #pragma unroll 4
        for (int d = 0; d < DH; d++) {
            float s = s_S[d * 17 + c];
            a0 += s_w[r0 * SP + d] * s;
            a1 += s_w[r1 * SP + d] * s;
        }
        s_un[r0 * 16 + c] = s_u[r0 * 16 + c] - a0;
        s_un[r1 * 16 + c] = s_u[r1 * 16 + c] - a1;
        __syncthreads();

        // ---- o = q @ S + att_local @ u_new ----
        float o0 = 0.f, o1 = 0.f;
        #pragma unroll 4
        for (int d = 0; d < DH; d++) {
            float s = s_S[d * 17 + c];
            o0 += s_q[r0 * SP + d] * s;
            o1 += s_q[r1 * SP + d] * s;
        }
        #pragma unroll
        for (int j = 0; j < CC; j++) {
            float un = s_un[j * 16 + c];
            o0 += s_attl[r0 * 32 + j] * un;
            o1 += s_attl[r1 * 32 + j] * un;
        }
        out[gb + r0 * DH + coff + c] = o0;
        out[gb + r1 * DH + coff + c] = o1;
        __syncthreads();   // all S reads complete before updating S

        // ---- S += k^T @ u_new  (8 d-rows per thread, float4 k loads) ----
        {
            float ac0=0.f,ac1=0.f,ac2=0.f,ac3=0.f,ac4=0.f,ac5=0.f,ac6=0.f,ac7=0.f;
            #pragma unroll 4
            for (int r = 0; r < CC; r++) {
                float un = s_un[r * 16 + c];
                float4 k0 = *(float4*)(s_k + r * SP + db);
                float4 k1 = *(float4*)(s_k + r * SP + db + 4);
                ac0 += k0.x * un; ac1 += k0.y * un; ac2 += k0.z * un; ac3 += k0.w * un;
                ac4 += k1.x * un; ac5 += k1.y * un; ac6 += k1.z * un; ac7 += k1.w * un;
            }
            s_S[(db + 0) * 17 + c] += ac0;
            s_S[(db + 1) * 17 + c] += ac1;
            s_S[(db + 2) * 17 + c] += ac2;
            s_S[(db + 3) * 17 + c] += ac3;
            s_S[(db + 4) * 17 + c] += ac4;
            s_S[(db + 5) * 17 + c] += ac5;
            s_S[(db + 6) * 17 + c] += ac6;
            s_S[(db + 7) * 17 + c] += ac7;
        }
        __syncthreads();
    }

    // ---- final state S, if the harness output includes it ----
    if (out_size >= (long long)O_ELEMS + (long long)S_ELEMS) {
        for (int i = tid; i < DH * DVS; i += 256) {
            int d = i >> 4, cc2 = i & 15;
            out[(size_t)O_ELEMS + ((size_t)head * DH + d) * DH + coff + cc2] =
                s_S[d * 17 + cc2];
        }
    }
}

// ===========================================================================
extern "C" void kernel_launch(void* const* d_in, const int* in_sizes, int n_in,
                              void* d_out, int out_size)
{
    const float* q    = (const float*)d_in[0];
    const float* k    = (const float*)d_in[1];
    const float* v    = (const float*)d_in[2];
    const float* beta = (const float*)d_in[3];
    float* out = (float*)d_out;

    const int smem1 = (4 * CC * SP + CC * 33 + CC + CC * 8) * (int)sizeof(float);
    const int smem2 = (3 * CC * SP + CC * CC + 2 * CC * DVS + DH * 17) * (int)sizeof(float);

    cudaFuncSetAttribute(deltanet_prep, cudaFuncAttributeMaxDynamicSharedMemorySize, smem1);
    cudaFuncSetAttribute(deltanet_scan, cudaFuncAttributeMaxDynamicSharedMemorySize, smem2);

    deltanet_prep<<<BH * NCH, 128, smem1>>>(q, k, v, beta);
    deltanet_scan<<<BH * NSLICE, 256, smem2>>>(out, (long long)out_size);
}

// round 8
// speedup vs baseline: 1.0160x; 1.0160x over previous
#include <cuda_runtime.h>
#include <cuda_bf16.h>

// Problem constants (from reference setup_inputs)
#define BH   16      // b*h = 2*8
#define LSEQ 4096
#define DH   128     // dk = dv
#define CC   32      // chunk size
#define NCH  128     // LSEQ / CC
#define SP   132     // padded shared row stride (floats)
#define NSLICE 8
#define DVS  16      // dv per scan CTA
#define O_ELEMS (BH * LSEQ * DH)   // 8388608
#define S_ELEMS (BH * DH * DH)     // 262144

// ---------------- device scratch (no allocations allowed) ----------------
__device__ float g_qn[BH * LSEQ * DH];
__device__ float g_kn[BH * LSEQ * DH];
__device__ float g_w [BH * LSEQ * DH];
__device__ float g_u [BH * LSEQ * DH];
__device__ float g_attl[BH * NCH * CC * CC];

// ===========================================================================
// Phase 1: per-(head,chunk) local work. Grid = 2048, 128 threads.
//   - l2norm q,k ; v*=beta ; kb = k*beta
//   - A = -(kb @ k^T) strictly-lower ; forward substitution ; +I ; bf16 round
//   - u = T @ v ; w = T @ kb ; att_local = tril(q @ k^T)  (incl. diagonal)
// ===========================================================================
extern "C" __global__ void __launch_bounds__(128)
deltanet_prep(const float* __restrict__ q, const float* __restrict__ k,
              const float* __restrict__ v, const float* __restrict__ beta)
{
    extern __shared__ float sm[];
    float* sq   = sm;                 // 32*132
    float* sk   = sq  + CC * SP;      // 32*132
    float* skb  = sk  + CC * SP;      // 32*132
    float* sv   = skb + CC * SP;      // 32*132
    float* sT   = sv  + CC * SP;      // 32*33
    float* sbet = sT  + CC * 33;      // 32
    float* sps  = sbet + CC;          // 32*8 partials (q:0..3, k:4..7)

    const int tid   = threadIdx.x;
    const int head  = blockIdx.x >> 7;        // / NCH
    const int chunk = blockIdx.x & (NCH - 1);
    const size_t gbase = ((size_t)head * LSEQ + (size_t)chunk * CC) * DH;

    // ---- load q,k,v tile (float4) into padded shared ----
    for (int i = tid; i < CC * DH / 4; i += 128) {
        int r = i >> 5, d4 = (i & 31) << 2;
        *(float4*)(sq + r * SP + d4) = *(const float4*)(q + gbase + r * DH + d4);
        *(float4*)(sk + r * SP + d4) = *(const float4*)(k + gbase + r * DH + d4);
        *(float4*)(sv + r * SP + d4) = *(const float4*)(v + gbase + r * DH + d4);
    }
    if (tid < CC) sbet[tid] = beta[(size_t)head * LSEQ + (size_t)chunk * CC + tid];
    __syncthreads();

    // ---- row sum-of-squares (4 partials per row) ----
    {
        int r = tid >> 2, p = tid & 3;
        float aq = 0.f, ak = 0.f;
        int d0 = p * 32;
        #pragma unroll 8
        for (int d = d0; d < d0 + 32; d++) {
            float xv = sq[r * SP + d]; aq += xv * xv;
            float yv = sk[r * SP + d]; ak += yv * yv;
        }
        sps[r * 8 + p]     = aq;
        sps[r * 8 + 4 + p] = ak;
    }
    __syncthreads();
    if (tid < CC) {
        float aq = sps[tid*8+0] + sps[tid*8+1] + sps[tid*8+2] + sps[tid*8+3];
        float ak = sps[tid*8+4] + sps[tid*8+5] + sps[tid*8+6] + sps[tid*8+7];
        sps[tid * 8]     = rsqrtf(aq + 1e-6f);
        sps[tid * 8 + 4] = rsqrtf(ak + 1e-6f);
    }
    __syncthreads();
    // ---- normalize + beta-scale ----
    for (int i = tid; i < CC * DH; i += 128) {
        int r = i >> 7, d = i & 127;
        int idx = r * SP + d;
        float qv = sq[idx] * sps[r * 8];
        float kv = sk[idx] * sps[r * 8 + 4];
        sq[idx]  = qv;
        sk[idx]  = kv;
        skb[idx] = kv * sbet[r];
        sv[idx] *= sbet[r];
    }
    __syncthreads();

    // ---- A[i][j] = -(kb[i] . k[j]) for j<i, else 0 ----
    {
        int i = tid >> 2, jq = tid & 3;
        float acc[8];
        #pragma unroll
        for (int jj = 0; jj < 8; jj++) acc[jj] = 0.f;
        for (int d = 0; d < DH; d++) {
            float kbv = skb[i * SP + d];
            #pragma unroll
            for (int jj = 0; jj < 8; jj++)
                acc[jj] += kbv * sk[(jq + 4 * jj) * SP + d];
        }
        #pragma unroll
        for (int jj = 0; jj < 8; jj++) {
            int j = jq + 4 * jj;
            sT[i * 33 + j] = (j < i) ? -acc[jj] : 0.f;
        }
    }
    __syncthreads();

    // ---- forward substitution on warp 0 (sequential over rows) ----
    if (tid < 32) {
        int m = tid;
        for (int i = 1; i < CC; i++) {
            float upd = 0.f;
            if (m < i) {
                for (int j = 0; j < i; j++)
                    upd += sT[i * 33 + j] * sT[j * 33 + m];
            }
            __syncwarp();
            if (m < i) sT[i * 33 + m] += upd;
            __syncwarp();
        }
    }
    __syncthreads();
    // ---- add I, then replicate reference bf16 round-trip ----
    for (int idx = tid; idx < CC * CC; idx += 128) {
        int i = idx >> 5, j = idx & 31;
        float tv = sT[i * 33 + j] + (i == j ? 1.f : 0.f);
        sT[i * 33 + j] = __bfloat162float(__float2bfloat16(tv));
    }
    __syncthreads();

    // ---- u = T @ (v*beta), w = T @ kb : thread = (row, 8 strided float4 cols) ----
    {
        int r = tid >> 2;
        int cb = (tid & 3) << 2;     // base col of float4; chunks at cb + 16*kk
        float4 au[8], aw[8];
        #pragma unroll
        for (int kk = 0; kk < 8; kk++) {
            au[kk] = make_float4(0.f, 0.f, 0.f, 0.f);
            aw[kk] = make_float4(0.f, 0.f, 0.f, 0.f);
        }
        for (int j = 0; j < CC; j++) {
            float t = sT[r * 33 + j];
            #pragma unroll
            for (int kk = 0; kk < 8; kk++) {
                float4 vv = *(float4*)(sv  + j * SP + cb + 16 * kk);
                float4 kb = *(float4*)(skb + j * SP + cb + 16 * kk);
                au[kk].x += t * vv.x; au[kk].y += t * vv.y;
                au[kk].z += t * vv.z; au[kk].w += t * vv.w;
                aw[kk].x += t * kb.x; aw[kk].y += t * kb.y;
                aw[kk].z += t * kb.z; aw[kk].w += t * kb.w;
            }
        }
        #pragma unroll
        for (int kk = 0; kk < 8; kk++) {
            *(float4*)(g_u + gbase + r * DH + cb + 16 * kk) = au[kk];
            *(float4*)(g_w + gbase + r * DH + cb + 16 * kk) = aw[kk];
        }
    }

    // ---- att_local = tril(q @ k^T) including diagonal ----
    {
        int i = tid >> 2, jq = tid & 3;
        float acc[8];
        #pragma unroll
        for (int jj = 0; jj < 8; jj++) acc[jj] = 0.f;
        for (int d = 0; d < DH; d++) {
            float qv = sq[i * SP + d];
            #pragma unroll
            for (int jj = 0; jj < 8; jj++)
                acc[jj] += qv * sk[(jq + 4 * jj) * SP + d];
        }
        size_t ab = ((size_t)(head * NCH + chunk)) * CC * CC;
        #pragma unroll
        for (int jj = 0; jj < 8; jj++) {
            int j = jq + 4 * jj;
            g_attl[ab + i * CC + j] = (j <= i) ? acc[jj] : 0.f;
        }
    }

    // ---- persist normalized q,k ----
    for (int i = tid; i < CC * DH / 4; i += 128) {
        int r = i >> 5, d4 = (i & 31) << 2;
        *(float4*)(g_qn + gbase + r * DH + d4) = *(float4*)(sq + r * SP + d4);
        *(float4*)(g_kn + gbase + r * DH + d4) = *(float4*)(sk + r * SP + d4);
    }
}

// ===========================================================================
// Phase 2: sequential scan over chunks, per (head, dv-slice).
// Grid = 16*8 = 128 CTAs, 256 threads. S[128 x 16] lives in shared (fp32).
// ===========================================================================
extern "C" __global__ void __launch_bounds__(256)
deltanet_scan(float* __restrict__ out, long long out_size)
{
    extern __shared__ float sm2[];
    float* s_w    = sm2;                 // 32*132
    float* s_q    = s_w    + CC * SP;    // 32*132
    float* s_k    = s_q    + CC * SP;    // 32*132
    float* s_attl = s_k    + CC * SP;    // 1024
    float* s_u    = s_attl + CC * CC;    // 512
    float* s_un   = s_u    + CC * DVS;   // 512
    float* s_S    = s_un   + CC * DVS;   // 128*17

    const int tid  = threadIdx.x;
    const int head = blockIdx.x >> 3;
    const int sl   = blockIdx.x & 7;
    const int coff = sl * DVS;

    for (int i = tid; i < DH * 17; i += 256) s_S[i] = 0.f;
    __syncthreads();

    const int c  = tid & 15;
    const int rr = tid >> 4;     // 0..15
    const int r0 = rr, r1 = rr + 16;
    const int db = rr * 8;       // S-update d base (reuse rr as d-group)

    for (int t = 0; t < NCH; t++) {
        const size_t gb = ((size_t)head * LSEQ + (size_t)t * CC) * DH;

        // ---- stage w, q, k, u-slice, att_local ----
        for (int i = tid; i < CC * DH / 4; i += 256) {
            int r = i >> 5, d4 = (i & 31) << 2;
            *(float4*)(s_w + r * SP + d4) = *(const float4*)(g_w  + gb + r * DH + d4);
            *(float4*)(s_q + r * SP + d4) = *(const float4*)(g_qn + gb + r * DH + d4);
            *(float4*)(s_k + r * SP + d4) = *(const float4*)(g_kn + gb + r * DH + d4);
        }
        for (int i = tid; i < CC * DVS; i += 256) {
            int r = i >> 4, cc2 = i & 15;
            s_u[i] = g_u[gb + r * DH + coff + cc2];
        }
        {
            size_t ab = ((size_t)(head * NCH + t)) * CC * CC;
            for (int i = tid; i < CC * CC; i += 256) s_attl[i] = g_attl[ab + i];
        }
        __syncthreads();

        // ---- u_new = u - w @ S ----
        float a0 = 0.f, a1 = 0.f;
        #pragma unroll 4
        for (int d = 0; d < DH; d++) {
            float s = s_S[d * 17 + c];
            a0 += s_w[r0 * SP + d] * s;
            a1 += s_w[r1 * SP + d] * s;
        }
        s_un[r0 * 16 + c] = s_u[r0 * 16 + c] - a0;
        s_un[r1 * 16 + c] = s_u[r1 * 16 + c] - a1;
        __syncthreads();

        // ---- o = q @ S + att_local @ u_new ----
        float o0 = 0.f, o1 = 0.f;
        #pragma unroll 4
        for (int d = 0; d < DH; d++) {
            float s = s_S[d * 17 + c];
            o0 += s_q[r0 * SP + d] * s;
            o1 += s_q[r1 * SP + d] * s;
        }
        #pragma unroll
        for (int j = 0; j < CC; j++) {
            float un = s_un[j * 16 + c];
            o0 += s_attl[r0 * 32 + j] * un;
            o1 += s_attl[r1 * 32 + j] * un;
        }
        out[gb + r0 * DH + coff + c] = o0;
        out[gb + r1 * DH + coff + c] = o1;
        __syncthreads();   // all S reads complete before updating S

        // ---- S += k^T @ u_new  (8 d-rows per thread, float4 k loads) ----
        {
            float ac0=0.f,ac1=0.f,ac2=0.f,ac3=0.f,ac4=0.f,ac5=0.f,ac6=0.f,ac7=0.f;
            #pragma unroll 4
            for (int r = 0; r < CC; r++) {
                float un = s_un[r * 16 + c];
                float4 k0 = *(float4*)(s_k + r * SP + db);
                float4 k1 = *(float4*)(s_k + r * SP + db + 4);
                ac0 += k0.x * un; ac1 += k0.y * un; ac2 += k0.z * un; ac3 += k0.w * un;
                ac4 += k1.x * un; ac5 += k1.y * un; ac6 += k1.z * un; ac7 += k1.w * un;
            }
            s_S[(db + 0) * 17 + c] += ac0;
            s_S[(db + 1) * 17 + c] += ac1;
            s_S[(db + 2) * 17 + c] += ac2;
            s_S[(db + 3) * 17 + c] += ac3;
            s_S[(db + 4) * 17 + c] += ac4;
            s_S[(db + 5) * 17 + c] += ac5;
            s_S[(db + 6) * 17 + c] += ac6;
            s_S[(db + 7) * 17 + c] += ac7;
        }
        __syncthreads();
    }

    // ---- final state S, if the harness output includes it ----
    if (out_size >= (long long)O_ELEMS + (long long)S_ELEMS) {
        for (int i = tid; i < DH * DVS; i += 256) {
            int d = i >> 4, cc2 = i & 15;
            out[(size_t)O_ELEMS + ((size_t)head * DH + d) * DH + coff + cc2] =
                s_S[d * 17 + cc2];
        }
    }
}

// ===========================================================================
extern "C" void kernel_launch(void* const* d_in, const int* in_sizes, int n_in,
                              void* d_out, int out_size)
{
    const float* q    = (const float*)d_in[0];
    const float* k    = (const float*)d_in[1];
    const float* v    = (const float*)d_in[2];
    const float* beta = (const float*)d_in[3];
    float* out = (float*)d_out;

    const int smem1 = (4 * CC * SP + CC * 33 + CC + CC * 8) * (int)sizeof(float);
    const int smem2 = (3 * CC * SP + CC * CC + 2 * CC * DVS + DH * 17) * (int)sizeof(float);

    cudaFuncSetAttribute(deltanet_prep, cudaFuncAttributeMaxDynamicSharedMemorySize, smem1);
    cudaFuncSetAttribute(deltanet_scan, cudaFuncAttributeMaxDynamicSharedMemorySize, smem2);

    deltanet_prep<<<BH * NCH, 128, smem1>>>(q, k, v, beta);
    deltanet_scan<<<BH * NSLICE, 256, smem2>>>(out, (long long)out_size);
}